// round 14
// baseline (speedup 1.0000x reference)
#include <cuda_runtime.h>
#include <cuda_fp16.h>
#include <cstdint>

// ---------------------------------------------------------------------------
// out[b,o,hw] = sum_c W[o,c] * relu(x[b,c,hw]*scale[c]+shift[c])
// Pass 1 (fuse): h[m,k] = fp16(relu(BN(x))), m=b*49+hw, k=c; W -> fp16.
// Pass 2 (gemm): fp16 mma.sync m16n8k16; grid (196,3), BM=64 BN=64 BK=64,
//   4-stage cp.async ring (3 groups in flight, wait_group 2), ONE barrier/iter,
//   register-double-buffered ldsm.
// ---------------------------------------------------------------------------
constexpr int CIN   = 2112;
constexpr int COUT  = 192;
constexpr int HWSZ  = 49;
constexpr int M_TOTAL = 256 * HWSZ;   // 12544
constexpr int BM = 64;
constexpr int BN = 64;
constexpr int BK = 64;
constexpr int NKT = CIN / BK;         // 33
constexpr int GRID_M = M_TOTAL / BM;  // 196

constexpr int STRIDE  = 144;                     // 64 halves + 8 pad
constexpr int A_STAGE = BM * STRIDE;             // 9216
constexpr int B_STAGE = BN * STRIDE;             // 9216
constexpr int NST     = 4;                       // ring depth
constexpr int SMEM_B0 = NST * A_STAGE;           // 36864
constexpr int SMEM_TOTAL = SMEM_B0 + NST * B_STAGE;  // 73728

__device__ __align__(16) __half g_h16[(size_t)M_TOTAL * CIN];
__device__ __align__(16) __half g_W16[COUT * CIN];

constexpr int CCH = 64;
constexpr int NCH = CIN / CCH;            // 33
constexpr int NT_CTA = 256 * NCH;         // 8448
constexpr int NW_CTA = (COUT * CIN) / 2048;  // 198

__device__ __forceinline__ uint32_t smem_u32(const void* p) {
    uint32_t a;
    asm("{ .reg .u64 t; cvta.to.shared.u64 t, %1; cvt.u32.u64 %0, t; }" : "=r"(a) : "l"(p));
    return a;
}
__device__ __forceinline__ uint32_t pack_h2(float lo, float hi) {
    __half2 h = __floats2half2_rn(lo, hi);
    return *reinterpret_cast<uint32_t*>(&h);
}
__device__ __forceinline__ void cp_async16(uint32_t saddr, const void* g) {
    asm volatile("cp.async.cg.shared.global [%0], [%1], 16;" :: "r"(saddr), "l"(g));
}
__device__ __forceinline__ void cp_commit() { asm volatile("cp.async.commit_group;"); }
__device__ __forceinline__ void cp_wait2()  { asm volatile("cp.async.wait_group 2;"); }
__device__ __forceinline__ void ldsm_x4(uint32_t* r, uint32_t addr) {
    asm volatile("ldmatrix.sync.aligned.m8n8.x4.shared.b16 {%0,%1,%2,%3}, [%4];"
                 : "=r"(r[0]), "=r"(r[1]), "=r"(r[2]), "=r"(r[3]) : "r"(addr));
}
__device__ __forceinline__ void mma16816(float& c0, float& c1, float& c2, float& c3,
                                         uint32_t a0, uint32_t a1, uint32_t a2, uint32_t a3,
                                         uint32_t b0, uint32_t b1) {
    asm volatile(
        "mma.sync.aligned.m16n8k16.row.col.f32.f16.f16.f32 "
        "{%0,%1,%2,%3}, {%4,%5,%6,%7}, {%8,%9}, {%0,%1,%2,%3};"
        : "+f"(c0), "+f"(c1), "+f"(c2), "+f"(c3)
        : "r"(a0), "r"(a1), "r"(a2), "r"(a3), "r"(b0), "r"(b1));
}

// ---------------------------------------------------------------------------
// Pass 1: BN+ReLU+fp16 transpose of x (vectorized) + W -> fp16
// ---------------------------------------------------------------------------
__global__ void __launch_bounds__(256)
fuse_kernel(const float* __restrict__ x,
            const float* __restrict__ gamma, const float* __restrict__ beta,
            const float* __restrict__ mean,  const float* __restrict__ var,
            const float* __restrict__ W) {
    const int tid = threadIdx.x;
    const int bid = blockIdx.x;

    if (bid >= NT_CTA) {   // W conversion: 512 float4 per CTA
        const int base4 = (bid - NT_CTA) * 512 + tid;
#pragma unroll
        for (int i = 0; i < 2; i++) {
            const int i4 = base4 + 256 * i;
            float4 f = *reinterpret_cast<const float4*>(W + (size_t)i4 * 4);
            uint2 u;
            u.x = pack_h2(f.x, f.y);
            u.y = pack_h2(f.z, f.w);
            *reinterpret_cast<uint2*>(g_W16 + (size_t)i4 * 4) = u;
        }
        return;
    }

    __shared__ float smf[CCH * 51];      // [c][hw], row stride 51
    __shared__ float ssc[CCH], ssh[CCH];

    const int b  = bid / NCH;
    const int c0 = (bid - b * NCH) * CCH;

    if (tid < CCH) {
        const int c = c0 + tid;
        float inv = rsqrtf(var[c] + 1e-5f);
        float s = gamma[c] * inv;
        ssc[tid] = s;
        ssh[tid] = fmaf(-mean[c], s, beta[c]);
    }
    __syncthreads();

    const float* src = x + ((size_t)b * CIN + c0) * HWSZ;
#pragma unroll
    for (int i = 0; i < 4; i++) {
        const int i4 = tid + 256 * i;
        if (i4 < 784) {
            float4 f = *reinterpret_cast<const float4*>(src + i4 * 4);
            const float vv[4] = {f.x, f.y, f.z, f.w};
#pragma unroll
            for (int e = 0; e < 4; e++) {
                const int idx = i4 * 4 + e;               // c*49 + hw
                const int c = (unsigned)idx / HWSZ;
                smf[idx + 2 * c] = fmaxf(fmaf(vv[e], ssc[c], ssh[c]), 0.0f);
            }
        }
    }
    __syncthreads();

#pragma unroll
    for (int i = 0; i < 4; i++) {
        const int j = tid + 256 * i;
        if (j < HWSZ * 16) {
            const int hw = j >> 4, cq = j & 15;
            const float v0 = smf[(4 * cq + 0) * 51 + hw];
            const float v1 = smf[(4 * cq + 1) * 51 + hw];
            const float v2 = smf[(4 * cq + 2) * 51 + hw];
            const float v3 = smf[(4 * cq + 3) * 51 + hw];
            uint2 u;
            u.x = pack_h2(v0, v1);
            u.y = pack_h2(v2, v3);
            *reinterpret_cast<uint2*>(g_h16 + (size_t)(b * HWSZ + hw) * CIN + c0 + 4 * cq) = u;
        }
    }
}

// ---------------------------------------------------------------------------
// Pass 2: GEMM. grid (196, 3); 128 threads = 2(M) x 2(N) warps, warp 32x32.
// ---------------------------------------------------------------------------
__global__ void __launch_bounds__(128, 3)
gemm_kernel(float* __restrict__ out) {
    extern __shared__ char smem[];
    const uint32_t sb = smem_u32(smem);
    const int tid = threadIdx.x;
    const int l = tid & 31;
    const int w = tid >> 5;
    const int m0 = blockIdx.x * BM;
    const int n0 = blockIdx.y * BN;

    const int g = l >> 2, t4 = l & 3;
    const int wm = (w >> 1) * 32;
    const int wn = (w & 1) * 32;
    // A frag: r0=[m0-7,k0-7] r1=[m8-15,k0-7] r2=[m0-7,k8-15] r3=[m8-15,k8-15]
    const int rAf = (l & 7) + (((l >> 3) & 1) << 3);
    const int cAf = (l >> 4) * 16;
    const uint32_t aFragBase = (uint32_t)((wm + rAf) * STRIDE + cAf);
    // B frag: r0=[n0-7,k0-7] r1=[n0-7,k8-15] r2=[n8-15,k0-7] r3=[n8-15,k8-15]
    const int rBf = (l & 7) + ((l >> 4) << 3);
    const int cBf = ((l >> 3) & 1) * 16;
    const uint32_t bFragBase = (uint32_t)((wn + rBf) * STRIDE + cBf);

    float acc[2][4][4];
#pragma unroll
    for (int mt = 0; mt < 2; mt++)
#pragma unroll
        for (int nt = 0; nt < 4; nt++)
#pragma unroll
            for (int c = 0; c < 4; c++) acc[mt][nt][c] = 0.0f;

    // cp.async: A 64 rows x 8 chunks = 512 (4/thread), B 64 x 8 = 512 (4/thread)
    auto cp_tile = [&](int kt) {
        const int stg = kt % NST;
        const uint32_t as = sb + stg * A_STAGE;
        const uint32_t bs = sb + SMEM_B0 + stg * B_STAGE;
        const __half* ah = g_h16 + (size_t)m0 * CIN + kt * BK;
#pragma unroll
        for (int i = 0; i < 4; i++) {
            const int idx = tid + 128 * i;
            const int row = idx >> 3, j = idx & 7;
            cp_async16(as + row * STRIDE + j * 16, ah + (size_t)row * CIN + j * 8);
        }
        const __half* bh = g_W16 + (size_t)n0 * CIN + kt * BK;
#pragma unroll
        for (int i = 0; i < 4; i++) {
            const int idx = tid + 128 * i;
            const int row = idx >> 3, j = idx & 7;
            cp_async16(bs + row * STRIDE + j * 16, bh + (size_t)row * CIN + j * 8);
        }
    };

    uint32_t af[2][2][4], bf[2][2][4];
    auto ldfrags = [&](uint32_t sA, uint32_t sB, int s, int buf) {
#pragma unroll
        for (int mt = 0; mt < 2; mt++)
            ldsm_x4(af[buf][mt], sA + aFragBase + mt * 16 * STRIDE + s * 32);
#pragma unroll
        for (int p = 0; p < 2; p++)
            ldsm_x4(bf[buf][p], sB + bFragBase + p * 16 * STRIDE + s * 32);
    };

    // prologue: 3 tiles in flight
    cp_tile(0); cp_commit();
    cp_tile(1); cp_commit();
    cp_tile(2); cp_commit();

#pragma unroll 1
    for (int kt = 0; kt < NKT; kt++) {
        cp_wait2();              // group kt complete (always-commit keeps pending = 3)
        __syncthreads();         // publish stage kt; license overwrite of (kt-1)%4

        const uint32_t sA = sb + (kt % NST) * A_STAGE;
        const uint32_t sB = sb + SMEM_B0 + (kt % NST) * B_STAGE;
        ldfrags(sA, sB, 0, 0);   // fragment chain starts BEFORE the cp burst
        if (kt + 3 < NKT) cp_tile(kt + 3);
        cp_commit();             // commit every iter (possibly empty group)

#pragma unroll
        for (int s = 0; s < 4; s++) {       // 4 k16-steps per BK=64
            if (s < 3) ldfrags(sA, sB, s + 1, (s + 1) & 1);
            const int cb = s & 1;
#pragma unroll
            for (int mt = 0; mt < 2; mt++)
#pragma unroll
                for (int p = 0; p < 2; p++) {
                    mma16816(acc[mt][2 * p][0], acc[mt][2 * p][1],
                             acc[mt][2 * p][2], acc[mt][2 * p][3],
                             af[cb][mt][0], af[cb][mt][1], af[cb][mt][2], af[cb][mt][3],
                             bf[cb][p][0], bf[cb][p][1]);
                    mma16816(acc[mt][2 * p + 1][0], acc[mt][2 * p + 1][1],
                             acc[mt][2 * p + 1][2], acc[mt][2 * p + 1][3],
                             af[cb][mt][0], af[cb][mt][1], af[cb][mt][2], af[cb][mt][3],
                             bf[cb][p][2], bf[cb][p][3]);
                }
        }
    }

    // epilogue
#pragma unroll
    for (int mt = 0; mt < 2; mt++) {
#pragma unroll
        for (int h = 0; h < 2; h++) {
            const int m = m0 + wm + mt * 16 + g + 8 * h;
            const int b = m / HWSZ, hw = m - b * HWSZ;
            float* op = out + (size_t)b * (COUT * HWSZ) + hw;
#pragma unroll
            for (int nt = 0; nt < 4; nt++) {
                const int n = n0 + wn + nt * 8 + 2 * t4;
                op[(size_t)n * HWSZ]       = acc[mt][nt][2 * h + 0];
                op[(size_t)(n + 1) * HWSZ] = acc[mt][nt][2 * h + 1];
            }
        }
    }
}

// ---------------------------------------------------------------------------
extern "C" void kernel_launch(void* const* d_in, const int* in_sizes, int n_in,
                              void* d_out, int out_size) {
    (void)in_sizes; (void)n_in; (void)out_size;
    const float* x     = (const float*)d_in[0];
    const float* gamma = (const float*)d_in[1];
    const float* beta  = (const float*)d_in[2];
    const float* rmean = (const float*)d_in[3];
    const float* rvar  = (const float*)d_in[4];
    const float* W     = (const float*)d_in[5];
    float* out = (float*)d_out;

    cudaFuncSetAttribute(gemm_kernel, cudaFuncAttributeMaxDynamicSharedMemorySize, SMEM_TOTAL);
    cudaFuncSetAttribute(gemm_kernel, cudaFuncAttributePreferredSharedMemoryCarveout, 100);

    fuse_kernel<<<NT_CTA + NW_CTA, 256>>>(x, gamma, beta, rmean, rvar, W);
    dim3 grid(GRID_M, 3);
    gemm_kernel<<<grid, 128, SMEM_TOTAL>>>(out);
}

// round 16
// speedup vs baseline: 1.0773x; 1.0773x over previous
#include <cuda_runtime.h>
#include <cuda_fp16.h>
#include <cstdint>

// ---------------------------------------------------------------------------
// out[b,o,hw] = sum_c W[o,c] * relu(x[b,c,hw]*scale[c]+shift[c])
// Pass 1 (fuse): h[m,k] = fp16(relu(BN(x))), m=b*49+hw, k=c; W -> fp16.
// Pass 2 (gemm): fp16 mma.sync m16n8k16; grid (196,3), BM=64 BN=64 BK=64.
//   WARP-SPECIALIZED: warp 4 = producer (all cp.async, signals stage-full via
//   cp.async.mbarrier.arrive.NOINC), warps 0-3 = consumers (mbarrier wait ->
//   ldsm -> mma -> arrive-empty). No __syncthreads/wait_group in main loop.
// ---------------------------------------------------------------------------
constexpr int CIN   = 2112;
constexpr int COUT  = 192;
constexpr int HWSZ  = 49;
constexpr int M_TOTAL = 256 * HWSZ;   // 12544
constexpr int BM = 64;
constexpr int BN = 64;
constexpr int BK = 64;
constexpr int NKT = CIN / BK;         // 33
constexpr int GRID_M = M_TOTAL / BM;  // 196

constexpr int STRIDE  = 144;                     // 64 halves + 8 pad
constexpr int A_STAGE = BM * STRIDE;             // 9216
constexpr int B_STAGE = BN * STRIDE;             // 9216
constexpr int NST     = 3;
constexpr int SMEM_B0  = NST * A_STAGE;          // 27648
constexpr int SMEM_BAR = SMEM_B0 + NST * B_STAGE;  // 55296 (full/empty pairs)
constexpr int SMEM_TOTAL = SMEM_BAR + NST * 16;  // 55344

__device__ __align__(16) __half g_h16[(size_t)M_TOTAL * CIN];
__device__ __align__(16) __half g_W16[COUT * CIN];

constexpr int CCH = 64;
constexpr int NCH = CIN / CCH;            // 33
constexpr int NT_CTA = 256 * NCH;         // 8448
constexpr int NW_CTA = (COUT * CIN) / 2048;  // 198

__device__ __forceinline__ uint32_t smem_u32(const void* p) {
    uint32_t a;
    asm("{ .reg .u64 t; cvta.to.shared.u64 t, %1; cvt.u32.u64 %0, t; }" : "=r"(a) : "l"(p));
    return a;
}
__device__ __forceinline__ uint32_t pack_h2(float lo, float hi) {
    __half2 h = __floats2half2_rn(lo, hi);
    return *reinterpret_cast<uint32_t*>(&h);
}
__device__ __forceinline__ void cp_async16(uint32_t saddr, const void* g) {
    asm volatile("cp.async.cg.shared.global [%0], [%1], 16;" :: "r"(saddr), "l"(g));
}
__device__ __forceinline__ void mbar_init(uint32_t a, uint32_t cnt) {
    asm volatile("mbarrier.init.shared.b64 [%0], %1;" :: "r"(a), "r"(cnt) : "memory");
}
__device__ __forceinline__ void mbar_arrive(uint32_t a) {
    asm volatile("mbarrier.arrive.shared.b64 _, [%0];" :: "r"(a) : "memory");
}
__device__ __forceinline__ void cp_mbar_arrive_noinc(uint32_t a) {
    // .noinc: this thread's async-completion counts against the INIT count
    // (default variant is self-balancing: +1 expect then +1 arrive -> net 0,
    //  which deadlocks a count-32 barrier. R15 bug.)
    asm volatile("cp.async.mbarrier.arrive.noinc.shared.b64 [%0];" :: "r"(a) : "memory");
}
__device__ __forceinline__ void mbar_wait(uint32_t a, uint32_t parity) {
    uint32_t done;
    asm volatile(
        "{\n\t.reg .pred p;\n\t"
        "mbarrier.try_wait.parity.acquire.cta.shared::cta.b64 p, [%1], %2;\n\t"
        "selp.b32 %0, 1, 0, p;\n\t}"
        : "=r"(done) : "r"(a), "r"(parity) : "memory");
    if (!done) {
        asm volatile(
            "{\n\t.reg .pred P1;\n\t"
            "WAIT_LOOP_%=:\n\t"
            "mbarrier.try_wait.parity.acquire.cta.shared::cta.b64 P1, [%0], %1, 0x989680;\n\t"
            "@P1 bra.uni WAIT_DONE_%=;\n\t"
            "bra.uni WAIT_LOOP_%=;\n\t"
            "WAIT_DONE_%=:\n\t}"
            :: "r"(a), "r"(parity) : "memory");
    }
}
__device__ __forceinline__ void ldsm_x4(uint32_t* r, uint32_t addr) {
    asm volatile("ldmatrix.sync.aligned.m8n8.x4.shared.b16 {%0,%1,%2,%3}, [%4];"
                 : "=r"(r[0]), "=r"(r[1]), "=r"(r[2]), "=r"(r[3]) : "r"(addr));
}
__device__ __forceinline__ void mma16816(float& c0, float& c1, float& c2, float& c3,
                                         uint32_t a0, uint32_t a1, uint32_t a2, uint32_t a3,
                                         uint32_t b0, uint32_t b1) {
    asm volatile(
        "mma.sync.aligned.m16n8k16.row.col.f32.f16.f16.f32 "
        "{%0,%1,%2,%3}, {%4,%5,%6,%7}, {%8,%9}, {%0,%1,%2,%3};"
        : "+f"(c0), "+f"(c1), "+f"(c2), "+f"(c3)
        : "r"(a0), "r"(a1), "r"(a2), "r"(a3), "r"(b0), "r"(b1));
}

// ---------------------------------------------------------------------------
// Pass 1: BN+ReLU+fp16 transpose of x (vectorized) + W -> fp16
// ---------------------------------------------------------------------------
__global__ void __launch_bounds__(256)
fuse_kernel(const float* __restrict__ x,
            const float* __restrict__ gamma, const float* __restrict__ beta,
            const float* __restrict__ mean,  const float* __restrict__ var,
            const float* __restrict__ W) {
    const int tid = threadIdx.x;
    const int bid = blockIdx.x;

    if (bid >= NT_CTA) {   // W conversion: 512 float4 per CTA
        const int base4 = (bid - NT_CTA) * 512 + tid;
#pragma unroll
        for (int i = 0; i < 2; i++) {
            const int i4 = base4 + 256 * i;
            float4 f = *reinterpret_cast<const float4*>(W + (size_t)i4 * 4);
            uint2 u;
            u.x = pack_h2(f.x, f.y);
            u.y = pack_h2(f.z, f.w);
            *reinterpret_cast<uint2*>(g_W16 + (size_t)i4 * 4) = u;
        }
        return;
    }

    __shared__ float smf[CCH * 51];      // [c][hw], row stride 51
    __shared__ float ssc[CCH], ssh[CCH];

    const int b  = bid / NCH;
    const int c0 = (bid - b * NCH) * CCH;

    if (tid < CCH) {
        const int c = c0 + tid;
        float inv = rsqrtf(var[c] + 1e-5f);
        float s = gamma[c] * inv;
        ssc[tid] = s;
        ssh[tid] = fmaf(-mean[c], s, beta[c]);
    }
    __syncthreads();

    const float* src = x + ((size_t)b * CIN + c0) * HWSZ;
#pragma unroll
    for (int i = 0; i < 4; i++) {
        const int i4 = tid + 256 * i;
        if (i4 < 784) {
            float4 f = *reinterpret_cast<const float4*>(src + i4 * 4);
            const float vv[4] = {f.x, f.y, f.z, f.w};
#pragma unroll
            for (int e = 0; e < 4; e++) {
                const int idx = i4 * 4 + e;               // c*49 + hw
                const int c = (unsigned)idx / HWSZ;
                smf[idx + 2 * c] = fmaxf(fmaf(vv[e], ssc[c], ssh[c]), 0.0f);
            }
        }
    }
    __syncthreads();

#pragma unroll
    for (int i = 0; i < 4; i++) {
        const int j = tid + 256 * i;
        if (j < HWSZ * 16) {
            const int hw = j >> 4, cq = j & 15;
            const float v0 = smf[(4 * cq + 0) * 51 + hw];
            const float v1 = smf[(4 * cq + 1) * 51 + hw];
            const float v2 = smf[(4 * cq + 2) * 51 + hw];
            const float v3 = smf[(4 * cq + 3) * 51 + hw];
            uint2 u;
            u.x = pack_h2(v0, v1);
            u.y = pack_h2(v2, v3);
            *reinterpret_cast<uint2*>(g_h16 + (size_t)(b * HWSZ + hw) * CIN + c0 + 4 * cq) = u;
        }
    }
}

// ---------------------------------------------------------------------------
// Pass 2: GEMM. grid (196, 3); 160 threads: warps 0-3 consume, warp 4 produces.
// ---------------------------------------------------------------------------
__global__ void __launch_bounds__(160, 3)
gemm_kernel(float* __restrict__ out) {
    extern __shared__ char smem[];
    const uint32_t sb = smem_u32(smem);
    const int tid = threadIdx.x;
    const int l = tid & 31;
    const int w = tid >> 5;
    const int m0 = blockIdx.x * BM;
    const int n0 = blockIdx.y * BN;

    // mbarriers: full[s] = SMEM_BAR + 16s, empty[s] = +8
    if (tid == 0) {
#pragma unroll
        for (int s = 0; s < NST; s++) {
            mbar_init(sb + SMEM_BAR + 16 * s, 32);        // full: 32 noinc async arrivals
            mbar_init(sb + SMEM_BAR + 16 * s + 8, 128);   // empty: 128 consumer threads
        }
    }
    __syncthreads();

    if (w == 4) {
        // ================= PRODUCER WARP =================
        const __half* ah = g_h16 + (size_t)m0 * CIN;
        const __half* bh = g_W16 + (size_t)n0 * CIN;
        int stage = 0;
        uint32_t phase = 1;                    // first ring pass: wait passes immediately
#pragma unroll 1
        for (int kt = 0; kt < NKT; kt++) {
            const uint32_t emp = sb + SMEM_BAR + 16 * stage + 8;
            mbar_wait(emp, phase);
            const uint32_t as = sb + stage * A_STAGE;
            const uint32_t bs = sb + SMEM_B0 + stage * B_STAGE;
            const __half* a0 = ah + kt * BK;
            const __half* b0 = bh + kt * BK;
#pragma unroll
            for (int i = 0; i < 16; i++) {     // A: 512 chunks / 32 threads
                const int idx = l + 32 * i;
                const int row = idx >> 3, j = idx & 7;
                cp_async16(as + row * STRIDE + j * 16, a0 + (size_t)row * CIN + j * 8);
            }
#pragma unroll
            for (int i = 0; i < 16; i++) {     // B: 512 chunks / 32 threads
                const int idx = l + 32 * i;
                const int row = idx >> 3, j = idx & 7;
                cp_async16(bs + row * STRIDE + j * 16, b0 + (size_t)row * CIN + j * 8);
            }
            cp_mbar_arrive_noinc(sb + SMEM_BAR + 16 * stage);  // full arrive on completion
            if (++stage == NST) { stage = 0; phase ^= 1; }
        }
        return;   // producer exits; consumers keep their smem/barrier state
    }

    // ================= CONSUMER WARPS (0-3) =================
    const int g = l >> 2, t4 = l & 3;
    const int wm = (w >> 1) * 32;
    const int wn = (w & 1) * 32;
    const int rAf = (l & 7) + (((l >> 3) & 1) << 3);
    const int cAf = (l >> 4) * 16;
    const uint32_t aFragBase = (uint32_t)((wm + rAf) * STRIDE + cAf);
    const int rBf = (l & 7) + ((l >> 4) << 3);
    const int cBf = ((l >> 3) & 1) * 16;
    const uint32_t bFragBase = (uint32_t)((wn + rBf) * STRIDE + cBf);

    float acc[2][4][4];
#pragma unroll
    for (int mt = 0; mt < 2; mt++)
#pragma unroll
        for (int nt = 0; nt < 4; nt++)
#pragma unroll
            for (int c = 0; c < 4; c++) acc[mt][nt][c] = 0.0f;

    uint32_t af[2][2][4], bf[2][2][4];
    auto ldfrags = [&](uint32_t sA, uint32_t sB, int s, int buf) {
#pragma unroll
        for (int mt = 0; mt < 2; mt++)
            ldsm_x4(af[buf][mt], sA + aFragBase + mt * 16 * STRIDE + s * 32);
#pragma unroll
        for (int p = 0; p < 2; p++)
            ldsm_x4(bf[buf][p], sB + bFragBase + p * 16 * STRIDE + s * 32);
    };

    int stage = 0;
    uint32_t phase = 0;
#pragma unroll 1
    for (int kt = 0; kt < NKT; kt++) {
        mbar_wait(sb + SMEM_BAR + 16 * stage, phase);     // wait full
        const uint32_t sA = sb + stage * A_STAGE;
        const uint32_t sB = sb + SMEM_B0 + stage * B_STAGE;
        ldfrags(sA, sB, 0, 0);
#pragma unroll
        for (int s = 0; s < 4; s++) {
            if (s < 3) ldfrags(sA, sB, s + 1, (s + 1) & 1);
            const int cb = s & 1;
#pragma unroll
            for (int mt = 0; mt < 2; mt++)
#pragma unroll
                for (int p = 0; p < 2; p++) {
                    mma16816(acc[mt][2 * p][0], acc[mt][2 * p][1],
                             acc[mt][2 * p][2], acc[mt][2 * p][3],
                             af[cb][mt][0], af[cb][mt][1], af[cb][mt][2], af[cb][mt][3],
                             bf[cb][p][0], bf[cb][p][1]);
                    mma16816(acc[mt][2 * p + 1][0], acc[mt][2 * p + 1][1],
                             acc[mt][2 * p + 1][2], acc[mt][2 * p + 1][3],
                             af[cb][mt][0], af[cb][mt][1], af[cb][mt][2], af[cb][mt][3],
                             bf[cb][p][2], bf[cb][p][3]);
                }
        }
        mbar_arrive(sb + SMEM_BAR + 16 * stage + 8);      // release stage (empty)
        if (++stage == NST) { stage = 0; phase ^= 1; }
    }

    // epilogue
#pragma unroll
    for (int mt = 0; mt < 2; mt++) {
#pragma unroll
        for (int h = 0; h < 2; h++) {
            const int m = m0 + wm + mt * 16 + g + 8 * h;
            const int b = m / HWSZ, hw = m - b * HWSZ;
            float* op = out + (size_t)b * (COUT * HWSZ) + hw;
#pragma unroll
            for (int nt = 0; nt < 4; nt++) {
                const int n = n0 + wn + nt * 8 + 2 * t4;
                op[(size_t)n * HWSZ]       = acc[mt][nt][2 * h + 0];
                op[(size_t)(n + 1) * HWSZ] = acc[mt][nt][2 * h + 1];
            }
        }
    }
}

// ---------------------------------------------------------------------------
extern "C" void kernel_launch(void* const* d_in, const int* in_sizes, int n_in,
                              void* d_out, int out_size) {
    (void)in_sizes; (void)n_in; (void)out_size;
    const float* x     = (const float*)d_in[0];
    const float* gamma = (const float*)d_in[1];
    const float* beta  = (const float*)d_in[2];
    const float* rmean = (const float*)d_in[3];
    const float* rvar  = (const float*)d_in[4];
    const float* W     = (const float*)d_in[5];
    float* out = (float*)d_out;

    cudaFuncSetAttribute(gemm_kernel, cudaFuncAttributeMaxDynamicSharedMemorySize, SMEM_TOTAL);
    cudaFuncSetAttribute(gemm_kernel, cudaFuncAttributePreferredSharedMemoryCarveout, 100);

    fuse_kernel<<<NT_CTA + NW_CTA, 256>>>(x, gamma, beta, rmean, rvar, W);
    dim3 grid(GRID_M, 3);
    gemm_kernel<<<grid, 160, SMEM_TOTAL>>>(out);
}